// round 9
// baseline (speedup 1.0000x reference)
#include <cuda_runtime.h>

// out[b,s,d] = x[b,s,d] + enc(s,d)
//   enc(s,d) = sin(s / 10000^(d/D)) if d even else cos(s / 10000^(d/D))
// Shapes: B=8, S=4096, D=1024, fp32. 268 MB traffic (algorithmic floor).
//
// FINAL — committed kernel of record (best measured: 43.488us end-to-end,
// ~5.8-6.0 TB/s, rel_err 1.8e-5).
//
// Session conclusion (R1-R8): this op is pinned at the mixed 1:1 R/W HBM3e
// ceiling (~74% of the 8 TB/s spec). Proven non-binding: occupancy (40%
// vs 82% identical), MLP (4 vs 8), access width (LDG.128 vs 256-bit v8),
// cache hints, block size (256 vs 512). Persistent grid-stride launch
// regressed 5% (broke front-batched read-burst structure). A non-reusing
// per-element kernel is compute-bound (~65us of sin/cos) and ruled out.
//
// Structure: one thread owns one (s, d..d+3) float4 column; computes the 4
// sin/cos encoding values ONCE (hidden under the 8 in-flight loads) and
// applies them to all 8 batch slices. Flat launch, loads front-batched
// (MLP=8), evict-first stores keep the write stream out of L2's way.

#define B_ 8
#define S_ 4096
#define D_ 1024
#define SD4_ ((S_ * D_) / 4)   // 1,048,576 float4 tiles per batch slice
#define TPB 512

__global__ __launch_bounds__(TPB) void pe_add_kernel(
    const float4* __restrict__ x, float4* __restrict__ out)
{
    const int idx4 = blockIdx.x * TPB + threadIdx.x;          // [0, SD4_)
    const int d0   = (idx4 & (D_ / 4 - 1)) << 2;              // element column in D
    const float sf = (float)(idx4 >> 8);                      // s = idx4 / 256

    // Front-batch all 8 batch-slice loads -> 8 outstanding LDG.128 per thread.
    float4 v[B_];
#pragma unroll
    for (int b = 0; b < B_; b++)
        v[b] = x[(long long)b * SD4_ + idx4];

    // Encoding float4, computed once, hidden under the in-flight loads.
    // angle(d) = s * 10000^(-d/D) = s * exp2(-d * log2(1e4)/D)
    const float c = -(13.287712379549449f / 1024.0f);
    const float e0 = sinf(sf * exp2f((float)(d0 + 0) * c));   // even d -> sin
    const float e1 = cosf(sf * exp2f((float)(d0 + 1) * c));   // odd d  -> cos
    const float e2 = sinf(sf * exp2f((float)(d0 + 2) * c));
    const float e3 = cosf(sf * exp2f((float)(d0 + 3) * c));

#pragma unroll
    for (int b = 0; b < B_; b++) {
        float4 r = v[b];
        r.x += e0; r.y += e1; r.z += e2; r.w += e3;
        __stcs(out + (long long)b * SD4_ + idx4, r);
    }
}

extern "C" void kernel_launch(void* const* d_in, const int* in_sizes, int n_in,
                              void* d_out, int out_size)
{
    const float4* x = (const float4*)d_in[0];
    float4* out = (float4*)d_out;
    pe_add_kernel<<<SD4_ / TPB, TPB>>>(x, out);
}

// round 10
// speedup vs baseline: 1.0007x; 1.0007x over previous
#include <cuda_runtime.h>

// out[b,s,d] = x[b,s,d] + enc(s,d)
//   enc(s,d) = sin(s / 10000^(d/D)) if d even else cos(s / 10000^(d/D))
// Shapes: B=8, S=4096, D=1024, fp32. 268 MB traffic (algorithmic floor).
//
// R10: kernel of record (43.49-43.52us reproducible x3, mixed 1:1 R/W HBM
// ceiling ~74% of spec) with the LAST untried dial: write-through stores
// (st.global.wt). Mechanism: .cs/default stores leave dirty L2 lines whose
// writeback bursts interleave with the demand-read stream at the DRAM bus;
// .wt pushes full coalesced 128B-line writes straight to the DRAM write
// queue, no dirty-line writeback coupling. All other axes proven
// non-binding across R1-R9 (occ, MLP, width, block size, launch shape).
//
// Structure: one thread owns one (s, d..d+3) float4 column; computes the 4
// sin/cos encoding values ONCE (hidden under the 8 in-flight loads) and
// applies them to all 8 batch slices. Flat launch, MLP=8 front-batched.

#define B_ 8
#define S_ 4096
#define D_ 1024
#define SD4_ ((S_ * D_) / 4)   // 1,048,576 float4 tiles per batch slice
#define TPB 512

__device__ __forceinline__ void stg_wt(float4* p, float4 v) {
    asm volatile("st.global.wt.v4.f32 [%0], {%1,%2,%3,%4};"
                 :: "l"(p), "f"(v.x), "f"(v.y), "f"(v.z), "f"(v.w)
                 : "memory");
}

__global__ __launch_bounds__(TPB) void pe_add_kernel(
    const float4* __restrict__ x, float4* __restrict__ out)
{
    const int idx4 = blockIdx.x * TPB + threadIdx.x;          // [0, SD4_)
    const int d0   = (idx4 & (D_ / 4 - 1)) << 2;              // element column in D
    const float sf = (float)(idx4 >> 8);                      // s = idx4 / 256

    // Front-batch all 8 batch-slice loads -> 8 outstanding LDG.128 per thread.
    float4 v[B_];
#pragma unroll
    for (int b = 0; b < B_; b++)
        v[b] = x[(long long)b * SD4_ + idx4];

    // Encoding float4, computed once, hidden under the in-flight loads.
    // angle(d) = s * 10000^(-d/D) = s * exp2(-d * log2(1e4)/D)
    const float c = -(13.287712379549449f / 1024.0f);
    const float e0 = sinf(sf * exp2f((float)(d0 + 0) * c));   // even d -> sin
    const float e1 = cosf(sf * exp2f((float)(d0 + 1) * c));   // odd d  -> cos
    const float e2 = sinf(sf * exp2f((float)(d0 + 2) * c));
    const float e3 = cosf(sf * exp2f((float)(d0 + 3) * c));

#pragma unroll
    for (int b = 0; b < B_; b++) {
        float4 r = v[b];
        r.x += e0; r.y += e1; r.z += e2; r.w += e3;
        stg_wt(out + (long long)b * SD4_ + idx4, r);
    }
}

extern "C" void kernel_launch(void* const* d_in, const int* in_sizes, int n_in,
                              void* d_out, int out_size)
{
    const float4* x = (const float4*)d_in[0];
    float4* out = (float4*)d_out;
    pe_add_kernel<<<SD4_ / TPB, TPB>>>(x, out);
}